// round 15
// baseline (speedup 1.0000x reference)
#include <cuda_runtime.h>
#include <cuda_bf16.h>

// RandomPool: out[b,c,i,j] = x[b,c, 2*i + sel/2, 2*j + sel%2]
// sel = select_idx[b/T, i*56+j], shared across C=128 channels and T=8 frames.
//
// Shapes (fixed):
//   x:          [32, 128, 112, 112] f32   (205.5 MB, streamed once)
//   select_idx: [4, 3136] i32             (49 KB, L2-hot, reused 1024x)
//   out:        [32, 128, 56, 56] f32     (51.4 MB, streamed once)
//
// R2 measured: 37.5us kernel, DRAM 80.7%, issue 15%. DRAM-bound.
// This candidate: 8 outputs/thread (MLP_p1 ~ 10 independent loads, half the
// index-math per byte), __ldcs on x / __stcs on out (evict-first streaming,
// keep L2 for the hot sel table).

#define SIDE   56
#define NP     3136        // 56*56
#define PLANE  12544       // 112*112
#define J8     7           // SIDE / 8

__global__ void __launch_bounds__(256, 8) randpool_kernel(
    const float* __restrict__ x,
    const int*   __restrict__ sel,
    float*       __restrict__ out,
    int total8)
{
    int t = blockIdx.x * blockDim.x + threadIdx.x;
    if (t >= total8) return;

    // t -> (bc, i, jj): jj indexes groups of 8 output columns
    int jj   = t % J8;
    int rest = t / J8;
    int i    = rest % SIDE;
    int bc   = rest / SIDE;          // b*128 + c, 0..4095
    int clip = bc >> 10;             // (bc/128)/8

    // 8 selection indices (two int4, 32B aligned; L2-hot)
    const int4* sp = reinterpret_cast<const int4*>(
        sel + clip * NP + i * SIDE + 8 * jj);
    const int4 sA = sp[0];
    const int4 sB = sp[1];

    // Both candidate source rows' 16-float spans: 8 independent float4
    // streaming loads, addresses independent of sel.
    const float* rowbase = x + (size_t)bc * PLANE + i * 224 + 16 * jj;
    float4 r0[4], r1[4];
#pragma unroll
    for (int q = 0; q < 4; q++)
        r0[q] = __ldcs(reinterpret_cast<const float4*>(rowbase) + q);
#pragma unroll
    for (int q = 0; q < 4; q++)
        r1[q] = __ldcs(reinterpret_cast<const float4*>(rowbase + 112) + q);

    const float* f0 = reinterpret_cast<const float*>(r0);
    const float* f1 = reinterpret_cast<const float*>(r1);
    const int s[8] = {sA.x, sA.y, sA.z, sA.w, sB.x, sB.y, sB.z, sB.w};

    float o[8];
#pragma unroll
    for (int p = 0; p < 8; p++) {
        // out col j0+p uses source cols 2p,2p+1 of row (s>>1); pick by s&1
        float a = (s[p] & 2) ? f1[2 * p]     : f0[2 * p];
        float b = (s[p] & 2) ? f1[2 * p + 1] : f0[2 * p + 1];
        o[p] = (s[p] & 1) ? b : a;
    }

    // out float4 index: base element 8*t -> float4 index 2*t
    float4* op = reinterpret_cast<float4*>(out) + 2 * t;
    __stcs(op,     make_float4(o[0], o[1], o[2], o[3]));
    __stcs(op + 1, make_float4(o[4], o[5], o[6], o[7]));
}

extern "C" void kernel_launch(void* const* d_in, const int* in_sizes, int n_in,
                              void* d_out, int out_size) {
    const float* x   = (const float*)d_in[0];
    const int*   sel = (const int*)d_in[1];
    float*       out = (float*)d_out;

    const int total8 = out_size / 8;          // 1,605,632
    const int threads = 256;
    const int blocks = (total8 + threads - 1) / threads;  // 6,272
    randpool_kernel<<<blocks, threads>>>(x, sel, out, total8);
}